// round 12
// baseline (speedup 1.0000x reference)
#include <cuda_runtime.h>

#define FULL 0xFFFFFFFFu

// Problem constants
#define BATCH 32
#define IN    2048
#define OUT   2048
#define KNUM  8
#define HDIM  512
#define KSZ   (IN * OUT)          // 4M elements per expert

#define IBLK   512                // i-range per main block
#define NCHUNK (IN / IBLK)        // 4
#define NQ     (IBLK / 64)        // 8 quarters of 64 i
#define OBLK   8                  // o's per block (8 warps x 1 o)
#define NOBLK  (OUT / OBLK)       // 256
#define XSTR   516                // x_s row stride

// Scratch (device globals; returned to initial state every call -> replay safe)
__device__ float    g_h[HDIM];        // zero-init; re-zeroed by last block
__device__ unsigned g_ticket;         // zero-init; reset by last block
__device__ float    g_alpha[KNUM];

// ---------------------------------------------------------------------------
// Fused MLP (single launch): 128 blocks x 512 thr. Partial cond@w1 -> atomic
// into g_h; zero out-slice. Last block (ticket) finishes relu/w2/softmax and
// resets scratch for graph replay.
// ---------------------------------------------------------------------------
__global__ void mlp_kernel(const float* __restrict__ cond,
                           const float* __restrict__ w1,
                           const float* __restrict__ b1,
                           const float* __restrict__ w2,
                           const float* __restrict__ b2,
                           float* __restrict__ out) {
    __shared__ float    h_s[HDIM];
    __shared__ float    s_s[KNUM];
    __shared__ unsigned rank_s;

    int j  = threadIdx.x;         // 0..511
    int p  = blockIdx.x;          // 0..127
    int i0 = p * 16;

    float s[8];
#pragma unroll
    for (int u = 0; u < 8; ++u)
        s[u] = cond[i0 + u] * w1[(i0 + u) * HDIM + j];
#pragma unroll
    for (int u = 0; u < 8; ++u)
        s[u] += cond[i0 + 8 + u] * w1[(i0 + 8 + u) * HDIM + j];
    float sum = ((s[0] + s[1]) + (s[2] + s[3])) + ((s[4] + s[5]) + (s[6] + s[7]));

    atomicAdd(&g_h[j], sum);
    out[p * HDIM + j] = 0.f;      // zero out for main's atomic accumulation

    __threadfence();
    __syncthreads();
    if (j == 0) rank_s = atomicAdd(&g_ticket, 1u);
    __syncthreads();
    if (rank_s != gridDim.x - 1) return;

    __threadfence();
    h_s[j] = fmaxf(g_h[j] + b1[j], 0.f);
    __syncthreads();

    int wid = j >> 5, lane = j & 31;
    if (wid < KNUM) {
        float sc = 0.f;
#pragma unroll
        for (int m = 0; m < HDIM / 32; ++m) {
            int jj = lane + m * 32;
            sc += h_s[jj] * w2[jj * KNUM + wid];
        }
#pragma unroll
        for (int off = 16; off; off >>= 1) sc += __shfl_xor_sync(FULL, sc, off);
        if (lane == 0) s_s[wid] = sc + b2[wid];
    }
    __syncthreads();
    if (j == 0) {
        float mx = -1e30f;
#pragma unroll
        for (int k = 0; k < KNUM; ++k) mx = fmaxf(mx, s_s[k]);
        float e[KNUM];
        float ssum = 0.f;
#pragma unroll
        for (int k = 0; k < KNUM; ++k) { e[k] = __expf(s_s[k] - mx); ssum += e[k]; }
        float inv = 1.f / ssum;
#pragma unroll
        for (int k = 0; k < KNUM; ++k) g_alpha[k] = e[k] * inv;
        g_ticket = 0;             // reset for next replay
    }
    g_h[j] = 0.f;                 // reset for next replay
}

// ---------------------------------------------------------------------------
// Main: out[b,o] (+)= sum_{i in chunk} (sum_k a_k KW[k,o,i]) * x[b,i]
// grid = NCHUNK*NOBLK = 1024 blocks x 256 threads, 3 blocks/SM (24 warps).
// Warp owns ONE o. Lane = (io = lane&15 -> 4-i slice, og = lane>>4 -> batch
// half). og half-warps load IDENTICAL kw addresses (HW dedup, no extra DRAM)
// but compute disjoint batch halves -> acc[16] per lane. Aggregated weights
// stay in registers; distance-1 quarter prefetch; no block syncs in loop.
// ---------------------------------------------------------------------------
__global__ __launch_bounds__(256, 3) void main_kernel(
        const float* __restrict__ x,    // [32, 2048]
        const float* __restrict__ kw,   // [8, 2048, 2048]
        const float* __restrict__ kb,   // [8, 2048]
        float* __restrict__ out) {      // [32, 2048]
    extern __shared__ float sm[];
    float* x_s    = sm;                           // 32 * 516 floats (66 KB)
    float* a_s    = sm + BATCH * XSTR;            // 8 (NOT aliased by part_s)
    float* part_s = sm;                           // alias x_s after compute:
                                                  // [ (b*8+oi)*17 + io ]

    int t    = threadIdx.x;
    int wid  = t >> 5;
    int lane = t & 31;
    int io   = lane & 15;
    int og   = lane >> 4;
    int ob   = blockIdx.x & (NOBLK - 1);          // 0..255
    int c    = blockIdx.x >> 8;                   // 0..3
    int i0   = c * IBLK;
    int o    = ob * OBLK + wid;                   // this warp's single o
    int b0   = og * 16;                           // this lane's batch half

    if (t < KNUM) a_s[t] = g_alpha[t];

    // thread's kw base: its o row, its 4-i slice of quarter 0
    const float* base = kw + (size_t)o * IN + i0 + io * 4;

    // preload quarter 0 (8 experts) BEFORE x staging
    float4 cur[KNUM];
#pragma unroll
    for (int k = 0; k < KNUM; ++k)
        cur[k] = *reinterpret_cast<const float4*>(base + (size_t)k * KSZ);

    // stage x tile: x_s[b][il] = x[b][i0+il], float4 (full 512-i tile)
    const float4* x4 = reinterpret_cast<const float4*>(x);
#pragma unroll
    for (int jj = 0; jj < (BATCH * IBLK) / (4 * 256); ++jj) {
        int idx = jj * 256 + t;                   // 0..4095 float4 units
        int b   = idx >> 7;                       // 128 f4 per row
        int il4 = idx & 127;
        *reinterpret_cast<float4*>(&x_s[b * XSTR + il4 * 4]) =
            x4[(b * IN + i0) / 4 + il4];
    }
    __syncthreads();

    float acc[16];
#pragma unroll
    for (int bb = 0; bb < 16; ++bb) acc[bb] = 0.f;

    for (int q = 0; q < NQ; ++q) {                // rolled: small body
        // ---- aggregate experts into registers (a from smem broadcast) ----
        float4 w4;
        {
            float a0 = a_s[0];
            w4.x = a0 * cur[0].x; w4.y = a0 * cur[0].y;
            w4.z = a0 * cur[0].z; w4.w = a0 * cur[0].w;
        }
#pragma unroll
        for (int k = 1; k < KNUM; ++k) {
            float ak = a_s[k];
            w4.x += ak * cur[k].x; w4.y += ak * cur[k].y;
            w4.z += ak * cur[k].z; w4.w += ak * cur[k].w;
        }

        // ---- prefetch next quarter (lands during this quarter's compute) ----
        if (q < NQ - 1) {
            const float* nb = base + (q + 1) * 64;
#pragma unroll
            for (int k = 0; k < KNUM; ++k)
                cur[k] = *reinterpret_cast<const float4*>(nb + (size_t)k * KSZ);
        }

        // ---- compute: 16 batches (this lane's half) x (1 LDS.128 + 4 FMA) ----
        const float* xrow = x_s + b0 * XSTR + q * 64 + io * 4;
#pragma unroll
        for (int bb = 0; bb < 16; ++bb) {
            float4 xq = *reinterpret_cast<const float4*>(xrow + bb * XSTR);
            acc[bb] += w4.x * xq.x;
            acc[bb] += w4.y * xq.y;
            acc[bb] += w4.z * xq.z;
            acc[bb] += w4.w * xq.w;
        }
    }

    // ---- epilogue: partials into smem (alias x_s), reduce over io ----
    __syncthreads();                  // all warps done reading x_s
#pragma unroll
    for (int bb = 0; bb < 16; ++bb)
        part_s[((b0 + bb) * OBLK + wid) * 17 + io] = acc[bb];
    __syncthreads();

    {
        int b   = t >> 3;             // 0..31
        int oi2 = t & 7;              // 0..7   (t == b*8+oi2)
        const float* p = &part_s[t * 17];
        float s0 = 0.f, s1 = 0.f;
#pragma unroll
        for (int j = 0; j < 16; j += 2) { s0 += p[j]; s1 += p[j + 1]; }
        float v = s0 + s1;
        if (c == 0) {                 // fold aggregated bias once
            int o2 = ob * OBLK + oi2;
            float bb2 = 0.f;
#pragma unroll
            for (int k = 0; k < KNUM; ++k) bb2 += a_s[k] * kb[k * OUT + o2];
            v += bb2;
        }
        atomicAdd(&out[b * OUT + ob * OBLK + oi2], v);
    }
}

// ---------------------------------------------------------------------------
extern "C" void kernel_launch(void* const* d_in, const int* in_sizes, int n_in,
                              void* d_out, int out_size) {
    const float* x    = (const float*)d_in[0];
    const float* cond = (const float*)d_in[1];
    const float* w1   = (const float*)d_in[2];
    const float* b1   = (const float*)d_in[3];
    const float* w2   = (const float*)d_in[4];
    const float* b2   = (const float*)d_in[5];
    const float* kw   = (const float*)d_in[6];
    const float* kb   = (const float*)d_in[7];
    float* out = (float*)d_out;

    const int SMEM_MAIN = (BATCH * XSTR + 8) * 4;   // ~66 KB
    static int smem_set = 0;
    if (!smem_set) {
        cudaFuncSetAttribute(main_kernel,
                             cudaFuncAttributeMaxDynamicSharedMemorySize,
                             SMEM_MAIN);
        smem_set = 1;
    }

    mlp_kernel<<<128, HDIM>>>(cond, w1, b1, w2, b2, out);
    main_kernel<<<NCHUNK * NOBLK, 256, SMEM_MAIN>>>(x, kw, kb, out);
}